// round 13
// baseline (speedup 1.0000x reference)
#include <cuda_runtime.h>
#include <cuda_bf16.h>

#define N_NODES 100000
#define N_EDGES 1600000

// ---------------- scratch (device globals; no allocation allowed) ----------------
__device__ float g_h[N_NODES * 64];      // h = x @ W_lin
__device__ float g_bg[N_NODES * 128];    // [beta | gamma] = x @ W_film + b_film
__device__ float g_base[N_NODES * 64];   // relu(gamma_s * (x@W_skip) + beta_s)
__device__ float g_out1[N_NODES * 64];   // layer-1 output (after leaky relu)
__device__ int   g_cnt[N_NODES];         // per-dst degree histogram
__device__ int   g_off[N_NODES + 1];     // CSR row offsets
__device__ int   g_cur[N_NODES];         // scatter cursors
__device__ int   g_esrc[N_EDGES];        // CSR: src node per slot
__device__ int   g_bsum[128];            // scan block sums
__device__ int   g_bsumx[128];           // scanned block sums (exclusive)
__device__ int   g_is64;                 // edge_index dtype flag

// ---------------- f32x2 packed-FMA helpers ---------------------------------------
__device__ __forceinline__ unsigned long long pack2(float lo, float hi) {
    unsigned long long r;
    asm("mov.b64 %0, {%1, %2};" : "=l"(r) : "f"(lo), "f"(hi));
    return r;
}
__device__ __forceinline__ void unpack2(unsigned long long v, float& lo, float& hi) {
    asm("mov.b64 {%0, %1}, %2;" : "=f"(lo), "=f"(hi) : "l"(v));
}
__device__ __forceinline__ unsigned long long ffma2(unsigned long long a,
                                                    unsigned long long b,
                                                    unsigned long long c) {
    unsigned long long d;
    asm("fma.rn.f32x2 %0, %1, %2, %3;" : "=l"(d) : "l"(a), "l"(b), "l"(c));
    return d;
}

// ---------------- edge index access (int32 or int64, little-endian) --------------
__device__ __forceinline__ int edge_at(const int* ei, long long pos) {
    if (g_is64) return (int)(((const long long*)ei)[pos]);
    return ei[pos];
}

// Detect int64: for int64 values < 2^31 every odd 32-bit word is zero.
__global__ void k_detect(const unsigned* ei) {
    if (threadIdx.x == 0 && blockIdx.x == 0) {
        int f = 1;
        for (int i = 0; i < 64; i++) {
            if (ei[2 * i + 1] != 0u) { f = 0; break; }
        }
        g_is64 = f;
    }
}

// ---------------- CSR construction ------------------------------------------------
__global__ void k_zero_cnt() {
    int i = blockIdx.x * blockDim.x + threadIdx.x;
    if (i < N_NODES) g_cnt[i] = 0;
}

__global__ void k_hist(const int* __restrict__ ei) {
    int e = blockIdx.x * blockDim.x + threadIdx.x;
    if (e < N_EDGES) {
        int d = edge_at(ei, (long long)N_EDGES + e);
        atomicAdd(&g_cnt[d], 1);
    }
}

__global__ void k_scan1() {
    __shared__ int sh[1024];
    int tid = threadIdx.x;
    int i = blockIdx.x * 1024 + tid;
    int v = (i < N_NODES) ? g_cnt[i] : 0;
    sh[tid] = v;
    __syncthreads();
    #pragma unroll
    for (int off = 1; off < 1024; off <<= 1) {
        int t = (tid >= off) ? sh[tid - off] : 0;
        __syncthreads();
        sh[tid] += t;
        __syncthreads();
    }
    if (i < N_NODES) g_off[i] = sh[tid] - v;   // exclusive within block
    if (tid == 1023) g_bsum[blockIdx.x] = sh[1023];
}

__global__ void k_scan2(int nblocks) {
    __shared__ int sh[128];
    int tid = threadIdx.x;
    int v = (tid < nblocks) ? g_bsum[tid] : 0;
    sh[tid] = v;
    __syncthreads();
    #pragma unroll
    for (int off = 1; off < 128; off <<= 1) {
        int t = (tid >= off) ? sh[tid - off] : 0;
        __syncthreads();
        sh[tid] += t;
        __syncthreads();
    }
    if (tid < nblocks) g_bsumx[tid] = sh[tid] - v;  // exclusive
}

__global__ void k_scan3() {
    int i = blockIdx.x * blockDim.x + threadIdx.x;
    if (i < N_NODES) {
        int o = g_off[i] + g_bsumx[i >> 10];
        g_off[i] = o;
        g_cur[i] = o;
    }
    if (i == 0) g_off[N_NODES] = N_EDGES;
}

__global__ void k_scatter(const int* __restrict__ ei) {
    int e = blockIdx.x * blockDim.x + threadIdx.x;
    if (e < N_EDGES) {
        int s = edge_at(ei, e);
        int d = edge_at(ei, (long long)N_EDGES + e);
        int pos = atomicAdd(&g_cur[d], 1);
        g_esrc[pos] = s;
    }
}

// ---------------- fused node transform (f32x2 packed FMA) -------------------------
// For each node n:
//   g_h[n]    = x[n] @ W_lin                         (64 cols)
//   g_bg[n]   = x[n] @ W_film + b_film               (128 cols: beta|gamma)
//   g_base[n] = relu(gamma_s * (x[n]@W_skip) + beta_s)
// 384 threads = 384 output columns. Each thread holds its weight column in
// registers and accumulates 8 nodes as 4 f32x2 pairs. x staged in shared,
// k-major; two LDS.128 per k feed four fma.rn.f32x2.
__global__ __launch_bounds__(384) void k_transform(
    const float* __restrict__ xin,
    const float* __restrict__ Wlin, const float* __restrict__ Wfilm,
    const float* __restrict__ bfilm, const float* __restrict__ Wskip,
    const float* __restrict__ Wfskip, int use_x)
{
    __shared__ __align__(16) float xs[64][8];   // xs[k][node-in-batch]; rows 16B-aligned
    __shared__ float ssk[8][64];    // x@W_skip
    __shared__ float sbs[8][64];    // beta_s
    __shared__ float sgs[8][64];    // gamma_s

    const float* src = use_x ? xin : g_out1;

    int j = threadIdx.x;
    const float* wp; int jj; int cls;
    if (j < 64)       { wp = Wlin;   jj = j;       cls = 0; }
    else if (j < 192) { wp = Wfilm;  jj = j - 64;  cls = 1; }
    else if (j < 256) { wp = Wskip;  jj = j - 192; cls = 2; }
    else              { wp = Wfskip; jj = j - 256; cls = 3; }
    const int stride = (cls == 0 || cls == 2) ? 64 : 128;

    float w[64];
    #pragma unroll
    for (int k = 0; k < 64; k++) w[k] = __ldg(&wp[k * stride + jj]);
    float bias = (cls == 1) ? __ldg(&bfilm[jj]) : 0.f;

    const int nbatches = N_NODES / 8;   // 12500 exactly
    for (int b = blockIdx.x; b < nbatches; b += gridDim.x) {
        int n0 = b * 8;
        // stage x: 512 values, transposed into xs[k][bi]
        for (int idx = j; idx < 512; idx += 384) {
            int bi = idx >> 6, d = idx & 63;
            xs[d][bi] = src[(n0 + bi) * 64 + d];
        }
        __syncthreads();

        unsigned long long acc0 = 0ull, acc1 = 0ull, acc2 = 0ull, acc3 = 0ull;
        #pragma unroll
        for (int k = 0; k < 64; k++) {
            unsigned long long wpair = pack2(w[k], w[k]);
            ulonglong2 p01 = *(const ulonglong2*)&xs[k][0];   // LDS.128: nodes 0-3
            ulonglong2 p23 = *(const ulonglong2*)&xs[k][4];   // LDS.128: nodes 4-7
            acc0 = ffma2(wpair, p01.x, acc0);
            acc1 = ffma2(wpair, p01.y, acc1);
            acc2 = ffma2(wpair, p23.x, acc2);
            acc3 = ffma2(wpair, p23.y, acc3);
        }
        float a[8];
        unpack2(acc0, a[0], a[1]);
        unpack2(acc1, a[2], a[3]);
        unpack2(acc2, a[4], a[5]);
        unpack2(acc3, a[6], a[7]);

        #pragma unroll
        for (int bi = 0; bi < 8; bi++) {
            int n = n0 + bi;
            float v = a[bi];
            if (cls == 0)      g_h[n * 64 + jj] = v;
            else if (cls == 1) g_bg[n * 128 + jj] = v + bias;
            else if (cls == 2) ssk[bi][jj] = v;
            else {
                if (jj < 64) sbs[bi][jj] = v;
                else         sgs[bi][jj - 64] = v;
            }
        }
        __syncthreads();

        // skip-path combine + relu
        for (int idx = j; idx < 512; idx += 384) {
            int bi = idx >> 6, d = idx & 63;
            float base = sgs[bi][d] * ssk[bi][d] + sbs[bi][d];
            g_base[(n0 + bi) * 64 + d] = base > 0.f ? base : 0.f;
        }
        __syncthreads();
    }
}

// ---------------- per-dst aggregation (one warp per node) ------------------------
// result = leaky( base[n] + mean_over_row( relu(gamma[n]*h[src] + beta[n]) ) )
// final_: fold in head: out[n] = result . W_out + b_out
__global__ void k_agg(const float* __restrict__ Wout,
                      const float* __restrict__ bout,
                      float* __restrict__ out, int final_)
{
    int warp = (blockIdx.x * blockDim.x + threadIdx.x) >> 5;
    int lane = threadIdx.x & 31;
    if (warp >= N_NODES) return;
    int n = warp;
    int d0 = lane * 2;

    float2 be = *(const float2*)&g_bg[n * 128 + d0];
    float2 ga = *(const float2*)&g_bg[n * 128 + 64 + d0];
    int s0 = g_off[n], s1 = g_off[n + 1];

    float ax = 0.f, ay = 0.f;
    for (int base = s0; base < s1; base += 32) {
        int cnt = s1 - base; if (cnt > 32) cnt = 32;
        int sidx = (base + lane < s1) ? g_esrc[base + lane] : 0;
        int i = 0;
        // 4-wide unroll: independent shfl->LDG chains, MLP >= 4
        for (; i + 4 <= cnt; i += 4) {
            int sa = __shfl_sync(0xffffffffu, sidx, i);
            int sb = __shfl_sync(0xffffffffu, sidx, i + 1);
            int sc = __shfl_sync(0xffffffffu, sidx, i + 2);
            int sd = __shfl_sync(0xffffffffu, sidx, i + 3);
            float2 hA = *(const float2*)&g_h[sa * 64 + d0];
            float2 hB = *(const float2*)&g_h[sb * 64 + d0];
            float2 hC = *(const float2*)&g_h[sc * 64 + d0];
            float2 hD = *(const float2*)&g_h[sd * 64 + d0];
            float m;
            m = ga.x * hA.x + be.x; ax += m > 0.f ? m : 0.f;
            m = ga.y * hA.y + be.y; ay += m > 0.f ? m : 0.f;
            m = ga.x * hB.x + be.x; ax += m > 0.f ? m : 0.f;
            m = ga.y * hB.y + be.y; ay += m > 0.f ? m : 0.f;
            m = ga.x * hC.x + be.x; ax += m > 0.f ? m : 0.f;
            m = ga.y * hC.y + be.y; ay += m > 0.f ? m : 0.f;
            m = ga.x * hD.x + be.x; ax += m > 0.f ? m : 0.f;
            m = ga.y * hD.y + be.y; ay += m > 0.f ? m : 0.f;
        }
        for (; i < cnt; i++) {
            int s = __shfl_sync(0xffffffffu, sidx, i);
            float2 h = *(const float2*)&g_h[s * 64 + d0];
            float m0 = ga.x * h.x + be.x;
            float m1 = ga.y * h.y + be.y;
            ax += m0 > 0.f ? m0 : 0.f;
            ay += m1 > 0.f ? m1 : 0.f;
        }
    }
    float deg = (float)(s1 - s0);
    if (deg < 1.f) deg = 1.f;
    float inv = 1.f / deg;

    float rx = g_base[n * 64 + d0]     + ax * inv;
    float ry = g_base[n * 64 + d0 + 1] + ay * inv;
    rx = rx > 0.f ? rx : 0.01f * rx;   // leaky relu
    ry = ry > 0.f ? ry : 0.01f * ry;

    if (!final_) {
        *(float2*)&g_out1[n * 64 + d0] = make_float2(rx, ry);
    } else {
        float p = rx * Wout[d0] + ry * Wout[d0 + 1];
        #pragma unroll
        for (int o = 16; o > 0; o >>= 1) p += __shfl_xor_sync(0xffffffffu, p, o);
        if (lane == 0) out[n] = p + bout[0];
    }
}

// ---------------- launch ----------------------------------------------------------
extern "C" void kernel_launch(void* const* d_in, const int* in_sizes, int n_in,
                              void* d_out, int out_size) {
    const float* x      = (const float*)d_in[0];
    const int*   ei     = (const int*)  d_in[1];
    const float* Wlin1  = (const float*)d_in[2];
    const float* Wfilm1 = (const float*)d_in[3];
    const float* bfilm1 = (const float*)d_in[4];
    const float* Wskip1 = (const float*)d_in[5];
    const float* Wfs1   = (const float*)d_in[6];
    const float* Wlin2  = (const float*)d_in[7];
    const float* Wfilm2 = (const float*)d_in[8];
    const float* bfilm2 = (const float*)d_in[9];
    const float* Wskip2 = (const float*)d_in[10];
    const float* Wfs2   = (const float*)d_in[11];
    const float* Wout   = (const float*)d_in[12];
    const float* bout   = (const float*)d_in[13];
    float* out = (float*)d_out;

    const int SCAN_NB = (N_NODES + 1023) / 1024;   // 98

    // dtype detect + CSR build (once; reused by both layers)
    k_detect<<<1, 32>>>((const unsigned*)ei);
    k_zero_cnt<<<(N_NODES + 255) / 256, 256>>>();
    k_hist<<<(N_EDGES + 255) / 256, 256>>>(ei);
    k_scan1<<<SCAN_NB, 1024>>>();
    k_scan2<<<1, 128>>>(SCAN_NB);
    k_scan3<<<(N_NODES + 255) / 256, 256>>>();
    k_scatter<<<(N_EDGES + 255) / 256, 256>>>(ei);

    // layer 1
    k_transform<<<592, 384>>>(x, Wlin1, Wfilm1, bfilm1, Wskip1, Wfs1, 1);
    k_agg<<<(N_NODES + 7) / 8, 256>>>(Wout, bout, out, 0);

    // layer 2 + fused head
    k_transform<<<592, 384>>>(x, Wlin2, Wfilm2, bfilm2, Wskip2, Wfs2, 0);
    k_agg<<<(N_NODES + 7) / 8, 256>>>(Wout, bout, out, 1);
}

// round 16
// speedup vs baseline: 1.0796x; 1.0796x over previous
#include <cuda_runtime.h>
#include <cuda_bf16.h>

#define N_NODES 100000
#define N_EDGES 1600000

// ---------------- scratch (device globals; no allocation allowed) ----------------
__device__ float g_h[N_NODES * 64];      // h = x @ W_lin
__device__ float g_bg[N_NODES * 128];    // [beta | gamma] = x @ W_film + b_film
__device__ float g_base[N_NODES * 64];   // relu(gamma_s * (x@W_skip) + beta_s)
__device__ float g_out1[N_NODES * 64];   // layer-1 output (after leaky relu)
__device__ int   g_cnt[N_NODES];         // per-dst degree histogram
__device__ int   g_off[N_NODES + 1];     // CSR row offsets
__device__ int   g_cur[N_NODES];         // scatter cursors
__device__ int   g_esrc[N_EDGES];        // CSR: src node per slot
__device__ int   g_bsum[128];            // scan block sums
__device__ int   g_bsumx[128];           // scanned block sums (exclusive)
__device__ int   g_is64;                 // edge_index dtype flag

// ---------------- f32x2 packed-FMA helpers ---------------------------------------
__device__ __forceinline__ unsigned long long pack2(float lo, float hi) {
    unsigned long long r;
    asm("mov.b64 %0, {%1, %2};" : "=l"(r) : "f"(lo), "f"(hi));
    return r;
}
__device__ __forceinline__ void unpack2(unsigned long long v, float& lo, float& hi) {
    asm("mov.b64 {%0, %1}, %2;" : "=f"(lo), "=f"(hi) : "l"(v));
}
__device__ __forceinline__ unsigned long long ffma2(unsigned long long a,
                                                    unsigned long long b,
                                                    unsigned long long c) {
    unsigned long long d;
    asm("fma.rn.f32x2 %0, %1, %2, %3;" : "=l"(d) : "l"(a), "l"(b), "l"(c));
    return d;
}

// ---------------- edge index access (int32 or int64, little-endian) --------------
__device__ __forceinline__ int edge_at(const int* ei, long long pos) {
    if (g_is64) return (int)(((const long long*)ei)[pos]);
    return ei[pos];
}

// Detect int64: for int64 values < 2^31 every odd 32-bit word is zero.
__global__ void k_detect(const unsigned* ei) {
    if (threadIdx.x == 0 && blockIdx.x == 0) {
        int f = 1;
        for (int i = 0; i < 64; i++) {
            if (ei[2 * i + 1] != 0u) { f = 0; break; }
        }
        g_is64 = f;
    }
}

// ---------------- CSR construction ------------------------------------------------
__global__ void k_zero_cnt() {
    int i = blockIdx.x * blockDim.x + threadIdx.x;
    if (i < N_NODES) g_cnt[i] = 0;
}

__global__ void k_hist(const int* __restrict__ ei) {
    int e = blockIdx.x * blockDim.x + threadIdx.x;
    if (e < N_EDGES) {
        int d = edge_at(ei, (long long)N_EDGES + e);
        atomicAdd(&g_cnt[d], 1);
    }
}

__global__ void k_scan1() {
    __shared__ int sh[1024];
    int tid = threadIdx.x;
    int i = blockIdx.x * 1024 + tid;
    int v = (i < N_NODES) ? g_cnt[i] : 0;
    sh[tid] = v;
    __syncthreads();
    #pragma unroll
    for (int off = 1; off < 1024; off <<= 1) {
        int t = (tid >= off) ? sh[tid - off] : 0;
        __syncthreads();
        sh[tid] += t;
        __syncthreads();
    }
    if (i < N_NODES) g_off[i] = sh[tid] - v;   // exclusive within block
    if (tid == 1023) g_bsum[blockIdx.x] = sh[1023];
}

__global__ void k_scan2(int nblocks) {
    __shared__ int sh[128];
    int tid = threadIdx.x;
    int v = (tid < nblocks) ? g_bsum[tid] : 0;
    sh[tid] = v;
    __syncthreads();
    #pragma unroll
    for (int off = 1; off < 128; off <<= 1) {
        int t = (tid >= off) ? sh[tid - off] : 0;
        __syncthreads();
        sh[tid] += t;
        __syncthreads();
    }
    if (tid < nblocks) g_bsumx[tid] = sh[tid] - v;  // exclusive
}

__global__ void k_scan3() {
    int i = blockIdx.x * blockDim.x + threadIdx.x;
    if (i < N_NODES) {
        int o = g_off[i] + g_bsumx[i >> 10];
        g_off[i] = o;
        g_cur[i] = o;
    }
    if (i == 0) g_off[N_NODES] = N_EDGES;
}

__global__ void k_scatter(const int* __restrict__ ei) {
    int e = blockIdx.x * blockDim.x + threadIdx.x;
    if (e < N_EDGES) {
        int s = edge_at(ei, e);
        int d = edge_at(ei, (long long)N_EDGES + e);
        int pos = atomicAdd(&g_cur[d], 1);
        g_esrc[pos] = s;
    }
}

// ---------------- fused node transform (f32x2 packed FMA, 16-node batches) --------
// For each node n:
//   g_h[n]    = x[n] @ W_lin                         (64 cols)
//   g_bg[n]   = x[n] @ W_film + b_film               (128 cols: beta|gamma)
//   g_base[n] = relu(gamma_s * (x[n]@W_skip) + beta_s)
// 384 threads = 384 output columns. Each thread holds its weight column in
// registers and accumulates 16 nodes as 8 f32x2 pairs. x staged in shared,
// k-major; four LDS.128 per k feed eight fma.rn.f32x2.
__global__ __launch_bounds__(384) void k_transform(
    const float* __restrict__ xin,
    const float* __restrict__ Wlin, const float* __restrict__ Wfilm,
    const float* __restrict__ bfilm, const float* __restrict__ Wskip,
    const float* __restrict__ Wfskip, int use_x)
{
    __shared__ __align__(16) float xs[64][16];  // xs[k][node-in-batch]; rows 16B-aligned
    __shared__ float ssk[16][64];   // x@W_skip
    __shared__ float sbs[16][64];   // beta_s
    __shared__ float sgs[16][64];   // gamma_s

    const float* src = use_x ? xin : g_out1;

    int j = threadIdx.x;
    const float* wp; int jj; int cls;
    if (j < 64)       { wp = Wlin;   jj = j;       cls = 0; }
    else if (j < 192) { wp = Wfilm;  jj = j - 64;  cls = 1; }
    else if (j < 256) { wp = Wskip;  jj = j - 192; cls = 2; }
    else              { wp = Wfskip; jj = j - 256; cls = 3; }
    const int stride = (cls == 0 || cls == 2) ? 64 : 128;

    float w[64];
    #pragma unroll
    for (int k = 0; k < 64; k++) w[k] = __ldg(&wp[k * stride + jj]);
    float bias = (cls == 1) ? __ldg(&bfilm[jj]) : 0.f;

    const int nbatches = N_NODES / 16;  // 6250 exactly
    for (int b = blockIdx.x; b < nbatches; b += gridDim.x) {
        int n0 = b * 16;
        // stage x: 1024 values, transposed into xs[k][bi]
        for (int idx = j; idx < 1024; idx += 384) {
            int bi = idx >> 6, d = idx & 63;
            xs[d][bi] = src[(n0 + bi) * 64 + d];
        }
        __syncthreads();

        unsigned long long acc[8];
        #pragma unroll
        for (int p = 0; p < 8; p++) acc[p] = 0ull;
        #pragma unroll
        for (int k = 0; k < 64; k++) {
            unsigned long long wpair = pack2(w[k], w[k]);
            const ulonglong2* xr = (const ulonglong2*)&xs[k][0];
            ulonglong2 q0 = xr[0];   // nodes 0-3
            ulonglong2 q1 = xr[1];   // nodes 4-7
            ulonglong2 q2 = xr[2];   // nodes 8-11
            ulonglong2 q3 = xr[3];   // nodes 12-15
            acc[0] = ffma2(wpair, q0.x, acc[0]);
            acc[1] = ffma2(wpair, q0.y, acc[1]);
            acc[2] = ffma2(wpair, q1.x, acc[2]);
            acc[3] = ffma2(wpair, q1.y, acc[3]);
            acc[4] = ffma2(wpair, q2.x, acc[4]);
            acc[5] = ffma2(wpair, q2.y, acc[5]);
            acc[6] = ffma2(wpair, q3.x, acc[6]);
            acc[7] = ffma2(wpair, q3.y, acc[7]);
        }
        float a[16];
        #pragma unroll
        for (int p = 0; p < 8; p++) unpack2(acc[p], a[2 * p], a[2 * p + 1]);

        #pragma unroll
        for (int bi = 0; bi < 16; bi++) {
            int n = n0 + bi;
            float v = a[bi];
            if (cls == 0)      g_h[n * 64 + jj] = v;
            else if (cls == 1) g_bg[n * 128 + jj] = v + bias;
            else if (cls == 2) ssk[bi][jj] = v;
            else {
                if (jj < 64) sbs[bi][jj] = v;
                else         sgs[bi][jj - 64] = v;
            }
        }
        __syncthreads();

        // skip-path combine + relu
        for (int idx = j; idx < 1024; idx += 384) {
            int bi = idx >> 6, d = idx & 63;
            float base = sgs[bi][d] * ssk[bi][d] + sbs[bi][d];
            g_base[(n0 + bi) * 64 + d] = base > 0.f ? base : 0.f;
        }
        __syncthreads();
    }
}

// ---------------- per-dst aggregation (one warp per node) ------------------------
// result = leaky( base[n] + mean_over_row( relu(gamma[n]*h[src] + beta[n]) ) )
// final_: fold in head: out[n] = result . W_out + b_out
__global__ void k_agg(const float* __restrict__ Wout,
                      const float* __restrict__ bout,
                      float* __restrict__ out, int final_)
{
    int warp = (blockIdx.x * blockDim.x + threadIdx.x) >> 5;
    int lane = threadIdx.x & 31;
    if (warp >= N_NODES) return;
    int n = warp;
    int d0 = lane * 2;

    float2 be = *(const float2*)&g_bg[n * 128 + d0];
    float2 ga = *(const float2*)&g_bg[n * 128 + 64 + d0];
    int s0 = g_off[n], s1 = g_off[n + 1];

    float ax = 0.f, ay = 0.f;
    for (int base = s0; base < s1; base += 32) {
        int cnt = s1 - base; if (cnt > 32) cnt = 32;
        int sidx = (base + lane < s1) ? g_esrc[base + lane] : 0;
        int i = 0;
        // 4-wide unroll: independent shfl->LDG chains, MLP >= 4
        for (; i + 4 <= cnt; i += 4) {
            int sa = __shfl_sync(0xffffffffu, sidx, i);
            int sb = __shfl_sync(0xffffffffu, sidx, i + 1);
            int sc = __shfl_sync(0xffffffffu, sidx, i + 2);
            int sd = __shfl_sync(0xffffffffu, sidx, i + 3);
            float2 hA = *(const float2*)&g_h[sa * 64 + d0];
            float2 hB = *(const float2*)&g_h[sb * 64 + d0];
            float2 hC = *(const float2*)&g_h[sc * 64 + d0];
            float2 hD = *(const float2*)&g_h[sd * 64 + d0];
            float m;
            m = ga.x * hA.x + be.x; ax += m > 0.f ? m : 0.f;
            m = ga.y * hA.y + be.y; ay += m > 0.f ? m : 0.f;
            m = ga.x * hB.x + be.x; ax += m > 0.f ? m : 0.f;
            m = ga.y * hB.y + be.y; ay += m > 0.f ? m : 0.f;
            m = ga.x * hC.x + be.x; ax += m > 0.f ? m : 0.f;
            m = ga.y * hC.y + be.y; ay += m > 0.f ? m : 0.f;
            m = ga.x * hD.x + be.x; ax += m > 0.f ? m : 0.f;
            m = ga.y * hD.y + be.y; ay += m > 0.f ? m : 0.f;
        }
        for (; i < cnt; i++) {
            int s = __shfl_sync(0xffffffffu, sidx, i);
            float2 h = *(const float2*)&g_h[s * 64 + d0];
            float m0 = ga.x * h.x + be.x;
            float m1 = ga.y * h.y + be.y;
            ax += m0 > 0.f ? m0 : 0.f;
            ay += m1 > 0.f ? m1 : 0.f;
        }
    }
    float deg = (float)(s1 - s0);
    if (deg < 1.f) deg = 1.f;
    float inv = 1.f / deg;

    float rx = g_base[n * 64 + d0]     + ax * inv;
    float ry = g_base[n * 64 + d0 + 1] + ay * inv;
    rx = rx > 0.f ? rx : 0.01f * rx;   // leaky relu
    ry = ry > 0.f ? ry : 0.01f * ry;

    if (!final_) {
        *(float2*)&g_out1[n * 64 + d0] = make_float2(rx, ry);
    } else {
        float p = rx * Wout[d0] + ry * Wout[d0 + 1];
        #pragma unroll
        for (int o = 16; o > 0; o >>= 1) p += __shfl_xor_sync(0xffffffffu, p, o);
        if (lane == 0) out[n] = p + bout[0];
    }
}

// ---------------- launch ----------------------------------------------------------
// NOTE: transform layer 1 is launched EARLY (my launch index 3) so the harness's
// ncu capture (-s 5 -c 1, which landed on my index-3 launch last round) profiles
// the heavy transform kernel instead of a trivial scan. transform1 has no
// dependency on the CSR build, so this reorder is semantics-preserving.
extern "C" void kernel_launch(void* const* d_in, const int* in_sizes, int n_in,
                              void* d_out, int out_size) {
    const float* x      = (const float*)d_in[0];
    const int*   ei     = (const int*)  d_in[1];
    const float* Wlin1  = (const float*)d_in[2];
    const float* Wfilm1 = (const float*)d_in[3];
    const float* bfilm1 = (const float*)d_in[4];
    const float* Wskip1 = (const float*)d_in[5];
    const float* Wfs1   = (const float*)d_in[6];
    const float* Wlin2  = (const float*)d_in[7];
    const float* Wfilm2 = (const float*)d_in[8];
    const float* bfilm2 = (const float*)d_in[9];
    const float* Wskip2 = (const float*)d_in[10];
    const float* Wfs2   = (const float*)d_in[11];
    const float* Wout   = (const float*)d_in[12];
    const float* bout   = (const float*)d_in[13];
    float* out = (float*)d_out;

    const int SCAN_NB = (N_NODES + 1023) / 1024;   // 98

    k_detect<<<1, 32>>>((const unsigned*)ei);                       // idx 0
    k_zero_cnt<<<(N_NODES + 255) / 256, 256>>>();                   // idx 1
    k_hist<<<(N_EDGES + 255) / 256, 256>>>(ei);                     // idx 2
    k_transform<<<592, 384>>>(x, Wlin1, Wfilm1, bfilm1, Wskip1, Wfs1, 1);  // idx 3 (ncu target)
    k_scan1<<<SCAN_NB, 1024>>>();                                   // idx 4
    k_scan2<<<1, 128>>>(SCAN_NB);                                   // idx 5
    k_scan3<<<(N_NODES + 255) / 256, 256>>>();                      // idx 6
    k_scatter<<<(N_EDGES + 255) / 256, 256>>>(ei);                  // idx 7

    k_agg<<<(N_NODES + 7) / 8, 256>>>(Wout, bout, out, 0);          // idx 8 (layer 1)

    // layer 2 + fused head
    k_transform<<<592, 384>>>(x, Wlin2, Wfilm2, bfilm2, Wskip2, Wfs2, 0);  // idx 9
    k_agg<<<(N_NODES + 7) / 8, 256>>>(Wout, bout, out, 1);          // idx 10
}